// round 14
// baseline (speedup 1.0000x reference)
#include <cuda_runtime.h>
#include <cuda_bf16.h>
#include <cstdint>
#include <math.h>

#define N_NODES 100000
#define D 128
#define E_EDGES 1600000
#define EPS 1e-5f
#define NT64 ((N_NODES + 63) / 64)   // 1563 tiles of 64 rows

// ---------------- scratch (device globals: no allocs allowed) ----------------
__device__ float  g_agg[(size_t)N_NODES * D];   // x + agg; then h2 (in-place)
__device__ double g_colsum[D];
__device__ double g_colsq [D];
__device__ int    g_idx_is64;

// ============================ helpers ========================================
__device__ __forceinline__ uint32_t smem_u32(const void* p) {
    uint32_t a;
    asm("{ .reg .u64 t; cvta.to.shared.u64 t, %1; cvt.u32.u64 %0, t; }"
        : "=r"(a) : "l"(p));
    return a;
}
__device__ __forceinline__ int bswz(int r, int j) {
    return r * 256 + ((((j ^ r) & 7) | (j & 8)) << 4);
}
__device__ __forceinline__ int idxA(int row, int col) {
    return row * 128 + (((col >> 2) ^ (row & 31)) << 2) + (col & 3);
}
__device__ __forceinline__ void ldmx4(uint32_t r[4], uint32_t addr) {
    asm volatile("ldmatrix.sync.aligned.m8n8.x4.shared.b16 {%0,%1,%2,%3}, [%4];"
                 : "=r"(r[0]), "=r"(r[1]), "=r"(r[2]), "=r"(r[3]) : "r"(addr));
}
__device__ __forceinline__ void mma_bf16(float c[4], const uint32_t a[4],
                                         uint32_t b0, uint32_t b1) {
    asm volatile(
        "mma.sync.aligned.m16n8k16.row.col.f32.bf16.bf16.f32 "
        "{%0,%1,%2,%3}, {%4,%5,%6,%7}, {%8,%9}, {%0,%1,%2,%3};"
        : "+f"(c[0]), "+f"(c[1]), "+f"(c[2]), "+f"(c[3])
        : "r"(a[0]), "r"(a[1]), "r"(a[2]), "r"(a[3]), "r"(b0), "r"(b1));
}
__device__ __forceinline__ void cp_async16(uint32_t s, const void* g, int src_sz) {
    asm volatile("cp.async.cg.shared.global [%0], [%1], 16, %2;"
                 :: "r"(s), "l"(g), "r"(src_sz) : "memory");
}
__device__ __forceinline__ void cp_commit() {
    asm volatile("cp.async.commit_group;" ::: "memory");
}
__device__ __forceinline__ void cp_wait0() {
    asm volatile("cp.async.wait_group 0;" ::: "memory");
}
__device__ __forceinline__ uint32_t pack_hi(float a, float b) {
    __nv_bfloat16 h0 = __float2bfloat16(a), h1 = __float2bfloat16(b);
    return (uint32_t)__bfloat16_as_ushort(h0)
         | ((uint32_t)__bfloat16_as_ushort(h1) << 16);
}
__device__ __forceinline__ uint32_t pack_lo(float a, float b) {
    __nv_bfloat16 h0 = __float2bfloat16(a), h1 = __float2bfloat16(b);
    __nv_bfloat16 l0 = __float2bfloat16(a - __bfloat162float(h0));
    __nv_bfloat16 l1 = __float2bfloat16(b - __bfloat162float(h1));
    return (uint32_t)__bfloat16_as_ushort(l0)
         | ((uint32_t)__bfloat16_as_ushort(l1) << 16);
}

// ---------------- kernel 1: zero BN accums, detect idx dtype (tiny) ---------
__global__ void init_small_kernel(const int* __restrict__ ei32) {
    if (threadIdx.x < D) {
        g_colsum[threadIdx.x] = 0.0;
        g_colsq [threadIdx.x] = 0.0;
    }
    if (threadIdx.x == 0) {
        int is64 = 1;
        #pragma unroll 1
        for (int k = 0; k < 128; k++)
            if (ei32[2 * k + 1] != 0) { is64 = 0; break; }
        g_idx_is64 = is64;
    }
}

// ---------------- kernel 2: scatter-add, one warp per edge ------------------
__device__ __forceinline__ void red_add_v4(float* addr, float4 v) {
    asm volatile("red.global.add.v4.f32 [%0], {%1,%2,%3,%4};"
                 :: "l"(addr), "f"(v.x), "f"(v.y), "f"(v.z), "f"(v.w) : "memory");
}
__global__ void scatter_kernel(const float* __restrict__ x,
                               const void* __restrict__ ei_raw) {
    int w    = (blockIdx.x * blockDim.x + threadIdx.x) >> 5;
    int lane = threadIdx.x & 31;
    if (w >= E_EDGES) return;
    int r, c;
    if (g_idx_is64) {
        const long long* ei = (const long long*)ei_raw;
        r = (int)__ldg(ei + w);
        c = (int)__ldg(ei + E_EDGES + w);
    } else {
        const int* ei = (const int*)ei_raw;
        r = __ldg(ei + w);
        c = __ldg(ei + E_EDGES + w);
    }
    float4 v = *reinterpret_cast<const float4*>(x + (size_t)c * D + lane * 4);
    red_add_v4(g_agg + (size_t)r * D + lane * 4, v);
}

// ---------------- fused MLP kernel (R12 structure, verbatim) ----------------
#define MLP_THREADS 512
#define SO_W1H  0
#define SO_W1L  32768
#define SO_W2H  65536
#define SO_W2L  98304
#define SO_A    131072     // Ahi 16384 | Alo 16384 ; OUT f32 aliases all 32768
#define SO_MID  163840
#define SO_STG  196608
#define SO_B1   229376
#define SO_B2   229888
#define SO_CS   230400
#define SO_CQ   230912
#define SM_BYTES 231424

__global__ __launch_bounds__(MLP_THREADS, 1)
void fused_mlp_kernel(const float* __restrict__ W1, const float* __restrict__ b1,
                      const float* __restrict__ W2, const float* __restrict__ b2) {
    extern __shared__ char smc[];
    float* OUT = (float*)(smc + SO_A);
    float* STG = (float*)(smc + SO_STG);
    float* B1S = (float*)(smc + SO_B1);
    float* B2S = (float*)(smc + SO_B2);
    float* CS  = (float*)(smc + SO_CS);
    float* CQ  = (float*)(smc + SO_CQ);
    const uint32_t sb = smem_u32(smc);

    const int tid    = threadIdx.x;
    const int lane   = tid & 31;
    const int warp   = tid >> 5;
    const int warp_m = warp & 3;
    const int warp_n = warp >> 2;
    const int gid    = lane >> 2;
    const int tig    = lane & 3;

    float* io = g_agg;

    for (int i4 = tid; i4 < 4096; i4 += MLP_THREADS) {
        int k  = i4 >> 5;
        int c4 = i4 & 31;
        float4 v1 = ((const float4*)W1)[i4];
        float4 v2 = ((const float4*)W2)[i4];
        #pragma unroll
        for (int e = 0; e < 4; e++) {
            float a = (e == 0) ? v1.x : (e == 1) ? v1.y : (e == 2) ? v1.z : v1.w;
            float b = (e == 0) ? v2.x : (e == 1) ? v2.y : (e == 2) ? v2.z : v2.w;
            int n = c4 * 4 + e;
            int off = bswz(n, k >> 3) + (k & 7) * 2;
            __nv_bfloat16 ah = __float2bfloat16(a);
            __nv_bfloat16 bh = __float2bfloat16(b);
            *(__nv_bfloat16*)(smc + SO_W1H + off) = ah;
            *(__nv_bfloat16*)(smc + SO_W1L + off) = __float2bfloat16(a - __bfloat162float(ah));
            *(__nv_bfloat16*)(smc + SO_W2H + off) = bh;
            *(__nv_bfloat16*)(smc + SO_W2L + off) = __float2bfloat16(b - __bfloat162float(bh));
        }
    }
    if (tid < 128) {
        B1S[tid] = b1[tid];
        B2S[tid] = b2[tid];
        CS[tid]  = 0.f;
        CQ[tid]  = 0.f;
    }

    {
        int t0 = blockIdx.x;
        if (t0 < NT64) {
            int base = t0 << 6;
            #pragma unroll
            for (int q = 0; q < 4; q++) {
                int ch  = q * MLP_THREADS + tid;
                int row = ch >> 5, c4 = ch & 31;
                int sz  = (base + row < N_NODES) ? 16 : 0;
                cp_async16(sb + SO_STG + ch * 16,
                           (const float4*)io + (size_t)(base + row) * 32 + c4, sz);
            }
        }
        cp_commit();
    }

    const int rA0 = warp_m * 16 + (lane & 15);
    const int jAh = lane >> 4;
    const int rB0 = warp_n * 32 + (lane & 7) + ((lane >> 4) << 3);
    const int jBh = (lane >> 3) & 1;

    for (int t = blockIdx.x; t < NT64; t += gridDim.x) {
        const int base  = t << 6;
        const int valid = min(64, N_NODES - base);

        cp_wait0();
        __syncthreads();

        // ---- 1) split STG -> Ahi/Alo bf16 ------------------------------------
        #pragma unroll
        for (int q = 0; q < 2; q++) {
            int f   = q * MLP_THREADS + tid;
            int row = f >> 4, j = f & 15;
            const float4* src = (const float4*)(STG + row * 128 + j * 8);
            float4 v0 = src[0], v1 = src[1];
            uint32_t ph[4] = {pack_hi(v0.x, v0.y), pack_hi(v0.z, v0.w),
                              pack_hi(v1.x, v1.y), pack_hi(v1.z, v1.w)};
            uint32_t pl[4] = {pack_lo(v0.x, v0.y), pack_lo(v0.z, v0.w),
                              pack_lo(v1.x, v1.y), pack_lo(v1.z, v1.w)};
            int off = bswz(row, j);
            *(uint4*)(smc + SO_A + off)         = make_uint4(ph[0], ph[1], ph[2], ph[3]);
            *(uint4*)(smc + SO_A + 16384 + off) = make_uint4(pl[0], pl[1], pl[2], pl[3]);
        }
        __syncthreads();

        {
            int tn = t + gridDim.x;
            if (tn < NT64) {
                int nb = tn << 6;
                #pragma unroll
                for (int q = 0; q < 4; q++) {
                    int ch  = q * MLP_THREADS + tid;
                    int row = ch >> 5, c4 = ch & 31;
                    int sz  = (nb + row < N_NODES) ? 16 : 0;
                    cp_async16(sb + SO_STG + ch * 16,
                               (const float4*)io + (size_t)(nb + row) * 32 + c4, sz);
                }
            }
            cp_commit();
        }

        float c[4][4];

        // ================= GEMM 1: mid = relu(A @ W1 + b1) ====================
        #pragma unroll
        for (int j = 0; j < 4; j++)
            #pragma unroll
            for (int e = 0; e < 4; e++) c[j][e] = 0.f;

        #pragma unroll 2
        for (int s = 0; s < 8; s++) {
            int jA = (s << 1) | jAh;
            uint32_t offA = (uint32_t)(rA0 * 256 + ((((jA ^ rA0) & 7) | (jA & 8)) << 4));
            int jB = (s << 1) | jBh;
            uint32_t offB = (uint32_t)(rB0 * 256 + ((((jB ^ rB0) & 7) | (jB & 8)) << 4));

            uint32_t ah[4], al[4], bh[2][4], bl[2][4];
            ldmx4(ah, sb + SO_A + offA);
            ldmx4(al, sb + SO_A + 16384 + offA);
            ldmx4(bh[0], sb + SO_W1H + offB);
            ldmx4(bh[1], sb + SO_W1H + offB + 4096);
            ldmx4(bl[0], sb + SO_W1L + offB);
            ldmx4(bl[1], sb + SO_W1L + offB + 4096);

            #pragma unroll
            for (int j = 0; j < 4; j++) {
                int p = j >> 1, q2 = (j & 1) << 1;
                mma_bf16(c[j], ah, bh[p][q2], bh[p][q2 + 1]);
                mma_bf16(c[j], ah, bl[p][q2], bl[p][q2 + 1]);
                mma_bf16(c[j], al, bh[p][q2], bh[p][q2 + 1]);
            }
        }

        {
            int r0 = warp_m * 16 + gid;
            #pragma unroll
            for (int j = 0; j < 4; j++) {
                int cc = warp_n * 32 + j * 8 + 2 * tig;
                float v0 = fmaxf(c[j][0] + B1S[cc],     0.f);
                float v1 = fmaxf(c[j][1] + B1S[cc + 1], 0.f);
                float v2 = fmaxf(c[j][2] + B1S[cc],     0.f);
                float v3 = fmaxf(c[j][3] + B1S[cc + 1], 0.f);
                int o0 = bswz(r0,     cc >> 3) + 4 * tig;
                int o1 = bswz(r0 + 8, cc >> 3) + 4 * tig;
                *(uint32_t*)(smc + SO_MID + o0)         = pack_hi(v0, v1);
                *(uint32_t*)(smc + SO_MID + 16384 + o0) = pack_lo(v0, v1);
                *(uint32_t*)(smc + SO_MID + o1)         = pack_hi(v2, v3);
                *(uint32_t*)(smc + SO_MID + 16384 + o1) = pack_lo(v2, v3);
            }
        }
        __syncthreads();

        // ================= GEMM 2: h2 = mid @ W2 + b2 =========================
        #pragma unroll
        for (int j = 0; j < 4; j++)
            #pragma unroll
            for (int e = 0; e < 4; e++) c[j][e] = 0.f;

        #pragma unroll 2
        for (int s = 0; s < 8; s++) {
            int jA = (s << 1) | jAh;
            uint32_t offA = (uint32_t)(rA0 * 256 + ((((jA ^ rA0) & 7) | (jA & 8)) << 4));
            int jB = (s << 1) | jBh;
            uint32_t offB = (uint32_t)(rB0 * 256 + ((((jB ^ rB0) & 7) | (jB & 8)) << 4));

            uint32_t ah[4], al[4], bh[2][4], bl[2][4];
            ldmx4(ah, sb + SO_MID + offA);
            ldmx4(al, sb + SO_MID + 16384 + offA);
            ldmx4(bh[0], sb + SO_W2H + offB);
            ldmx4(bh[1], sb + SO_W2H + offB + 4096);
            ldmx4(bl[0], sb + SO_W2L + offB);
            ldmx4(bl[1], sb + SO_W2L + offB + 4096);

            #pragma unroll
            for (int j = 0; j < 4; j++) {
                int p = j >> 1, q2 = (j & 1) << 1;
                mma_bf16(c[j], ah, bh[p][q2], bh[p][q2 + 1]);
                mma_bf16(c[j], ah, bl[p][q2], bl[p][q2 + 1]);
                mma_bf16(c[j], al, bh[p][q2], bh[p][q2 + 1]);
            }
        }

        {
            int r0 = warp_m * 16 + gid;
            #pragma unroll
            for (int j = 0; j < 4; j++) {
                int cc = warp_n * 32 + j * 8 + 2 * tig;
                float v0 = c[j][0] + B2S[cc];
                float v1 = c[j][1] + B2S[cc + 1];
                float v2 = c[j][2] + B2S[cc];
                float v3 = c[j][3] + B2S[cc + 1];
                *(float2*)&OUT[idxA(r0,     cc)] = make_float2(v0, v1);
                *(float2*)&OUT[idxA(r0 + 8, cc)] = make_float2(v2, v3);
            }
        }
        __syncthreads();

        {
            int col  = tid >> 2;
            int quar = tid & 3;
            int rbeg = quar * 16;
            int rend = min(rbeg + 16, valid);
            float s = 0.f, q = 0.f;
            for (int r = rbeg; r < rend; r++) {
                float v = OUT[idxA(r, col)];
                s += v; q += v * v;
            }
            atomicAdd(&CS[col], s);
            atomicAdd(&CQ[col], q);
        }
        #pragma unroll
        for (int q = 0; q < 4; q++) {
            int f   = q * MLP_THREADS + tid;
            int row = f >> 5, c4 = f & 31;
            if (row < valid) {
                int off = row * 128 + ((c4 ^ (row & 31)) << 2);
                float4 v = *(const float4*)(OUT + off);
                ((float4*)io)[(size_t)(base + row) * 32 + c4] = v;
            }
        }
    }

    __syncthreads();
    if (tid < 128) {
        atomicAdd(&g_colsum[tid], (double)CS[tid]);
        atomicAdd(&g_colsq [tid], (double)CQ[tid]);
    }
}

// ---------------- apply BN (per-block FLOAT coefficients) --------------------
__global__ void bn_apply_kernel(const float* __restrict__ gamma,
                                const float* __restrict__ beta,
                                float* __restrict__ out) {
    __shared__ float sc[D], sh[D];
    if (threadIdx.x < D) {
        int j = threadIdx.x;
        float sum = (float)g_colsum[j];
        float sq  = (float)g_colsq[j];
        float invN = 1.0f / (float)N_NODES;
        float mean = sum * invN;
        float var  = fmaxf(sq * invN - mean * mean, 0.f);
        float inv  = rsqrtf(var + EPS);
        float s    = gamma[j] * inv;
        sc[j] = s;
        sh[j] = beta[j] - mean * s;
    }
    __syncthreads();
    size_t i  = (size_t)blockIdx.x * blockDim.x + threadIdx.x;
    size_t n4 = (size_t)N_NODES * D / 4;
    if (i < n4) {
        int c = (int)((i & 31) << 2);
        float4 h = reinterpret_cast<const float4*>(g_agg)[i];
        float4 o;
        o.x = h.x * sc[c + 0] + sh[c + 0];
        o.y = h.y * sc[c + 1] + sh[c + 1];
        o.z = h.z * sc[c + 2] + sh[c + 2];
        o.w = h.w * sc[c + 3] + sh[c + 3];
        reinterpret_cast<float4*>(out)[i] = o;
    }
}

// ---------------- launcher ------------------------------------------------------
extern "C" void kernel_launch(void* const* d_in, const int* in_sizes, int n_in,
                              void* d_out, int out_size) {
    const float* x     = (const float*)d_in[0];
    const void*  ei    = d_in[1];
    const float* W1    = (const float*)d_in[2];
    const float* b1    = (const float*)d_in[3];
    const float* W2    = (const float*)d_in[4];
    const float* b2    = (const float*)d_in[5];
    const float* gamma = (const float*)d_in[6];
    const float* beta  = (const float*)d_in[7];
    float* out = (float*)d_out;

    cudaFuncSetAttribute(fused_mlp_kernel,
                         cudaFuncAttributeMaxDynamicSharedMemorySize, SM_BYTES);

    // init: g_agg = x via driver D2D copy (allowed, graph-capturable),
    // plus tiny kernel for BN accumulators + dtype detect
    void* agg_ptr = nullptr;
    cudaGetSymbolAddress(&agg_ptr, g_agg);
    cudaMemcpyAsync(agg_ptr, x, (size_t)N_NODES * D * sizeof(float),
                    cudaMemcpyDeviceToDevice, 0);
    init_small_kernel<<<1, 128>>>((const int*)ei);

    {
        int blocks = (E_EDGES + 7) / 8;   // 8 warps (256 threads) per block
        scatter_kernel<<<blocks, 256>>>(x, ei);
    }
    fused_mlp_kernel<<<152, MLP_THREADS, SM_BYTES>>>(W1, b1, W2, b2);
    {
        int n4 = N_NODES * D / 4;
        bn_apply_kernel<<<(n4 + 255) / 256, 256>>>(gamma, beta, out);
    }
}

// round 15
// speedup vs baseline: 1.4250x; 1.4250x over previous
#include <cuda_runtime.h>
#include <cuda_bf16.h>
#include <cstdint>
#include <math.h>

#define N_NODES 100000
#define D 128
#define E_EDGES 1600000
#define EPS 1e-5f
#define NT64 ((N_NODES + 63) / 64)   // 1563 tiles of 64 rows

// ---------------- scratch (device globals: no allocs allowed) ----------------
__device__ float  g_agg[(size_t)N_NODES * D];   // x + agg; then h2 (in-place)
__device__ double g_colsum[D];
__device__ double g_colsq [D];
__device__ int    g_idx_is64;

// ============================ helpers ========================================
__device__ __forceinline__ uint32_t smem_u32(const void* p) {
    uint32_t a;
    asm("{ .reg .u64 t; cvta.to.shared.u64 t, %1; cvt.u32.u64 %0, t; }"
        : "=r"(a) : "l"(p));
    return a;
}
__device__ __forceinline__ int bswz(int r, int j) {
    return r * 256 + ((((j ^ r) & 7) | (j & 8)) << 4);
}
__device__ __forceinline__ int idxA(int row, int col) {
    return row * 128 + (((col >> 2) ^ (row & 31)) << 2) + (col & 3);
}
__device__ __forceinline__ void ldmx4(uint32_t r[4], uint32_t addr) {
    asm volatile("ldmatrix.sync.aligned.m8n8.x4.shared.b16 {%0,%1,%2,%3}, [%4];"
                 : "=r"(r[0]), "=r"(r[1]), "=r"(r[2]), "=r"(r[3]) : "r"(addr));
}
__device__ __forceinline__ void mma_bf16(float c[4], const uint32_t a[4],
                                         uint32_t b0, uint32_t b1) {
    asm volatile(
        "mma.sync.aligned.m16n8k16.row.col.f32.bf16.bf16.f32 "
        "{%0,%1,%2,%3}, {%4,%5,%6,%7}, {%8,%9}, {%0,%1,%2,%3};"
        : "+f"(c[0]), "+f"(c[1]), "+f"(c[2]), "+f"(c[3])
        : "r"(a[0]), "r"(a[1]), "r"(a[2]), "r"(a[3]), "r"(b0), "r"(b1));
}
__device__ __forceinline__ void cp_async16(uint32_t s, const void* g, int src_sz) {
    asm volatile("cp.async.cg.shared.global [%0], [%1], 16, %2;"
                 :: "r"(s), "l"(g), "r"(src_sz) : "memory");
}
__device__ __forceinline__ void cp_commit() {
    asm volatile("cp.async.commit_group;" ::: "memory");
}
__device__ __forceinline__ void cp_wait0() {
    asm volatile("cp.async.wait_group 0;" ::: "memory");
}
__device__ __forceinline__ uint32_t pack_hi(float a, float b) {
    __nv_bfloat16 h0 = __float2bfloat16(a), h1 = __float2bfloat16(b);
    return (uint32_t)__bfloat16_as_ushort(h0)
         | ((uint32_t)__bfloat16_as_ushort(h1) << 16);
}
__device__ __forceinline__ uint32_t pack_lo(float a, float b) {
    __nv_bfloat16 h0 = __float2bfloat16(a), h1 = __float2bfloat16(b);
    __nv_bfloat16 l0 = __float2bfloat16(a - __bfloat162float(h0));
    __nv_bfloat16 l1 = __float2bfloat16(b - __bfloat162float(h1));
    return (uint32_t)__bfloat16_as_ushort(l0)
         | ((uint32_t)__bfloat16_as_ushort(l1) << 16);
}

// ---------------- kernel 1: agg = x, zero BN accums, detect idx dtype -------
__global__ void init_kernel(const float* __restrict__ x,
                            const int* __restrict__ ei32) {
    size_t i = (size_t)blockIdx.x * blockDim.x + threadIdx.x;
    size_t n4 = (size_t)N_NODES * D / 4;
    if (i < n4)
        reinterpret_cast<float4*>(g_agg)[i] = reinterpret_cast<const float4*>(x)[i];
    if (blockIdx.x == 0 && threadIdx.x < D) {
        g_colsum[threadIdx.x] = 0.0;
        g_colsq [threadIdx.x] = 0.0;
    }
    if (blockIdx.x == 0 && threadIdx.x == 0) {
        int is64 = 1;
        #pragma unroll 1
        for (int k = 0; k < 128; k++)
            if (ei32[2 * k + 1] != 0) { is64 = 0; break; }
        g_idx_is64 = is64;
    }
}

// ---------------- kernel 2: scatter-add, one warp per edge ------------------
__device__ __forceinline__ void red_add_v4(float* addr, float4 v) {
    asm volatile("red.global.add.v4.f32 [%0], {%1,%2,%3,%4};"
                 :: "l"(addr), "f"(v.x), "f"(v.y), "f"(v.z), "f"(v.w) : "memory");
}
__global__ void scatter_kernel(const float* __restrict__ x,
                               const void* __restrict__ ei_raw) {
    int w    = (blockIdx.x * blockDim.x + threadIdx.x) >> 5;
    int lane = threadIdx.x & 31;
    if (w >= E_EDGES) return;
    int r, c;
    if (g_idx_is64) {
        const long long* ei = (const long long*)ei_raw;
        r = (int)__ldg(ei + w);
        c = (int)__ldg(ei + E_EDGES + w);
    } else {
        const int* ei = (const int*)ei_raw;
        r = __ldg(ei + w);
        c = __ldg(ei + E_EDGES + w);
    }
    float4 v = *reinterpret_cast<const float4*>(x + (size_t)c * D + lane * 4);
    red_add_v4(g_agg + (size_t)r * D + lane * 4, v);
}

// ---------------- fused MLP kernel (R12 structure, verbatim) ----------------
#define MLP_THREADS 512
#define SO_W1H  0
#define SO_W1L  32768
#define SO_W2H  65536
#define SO_W2L  98304
#define SO_A    131072     // Ahi 16384 | Alo 16384 ; OUT f32 aliases all 32768
#define SO_MID  163840
#define SO_STG  196608
#define SO_B1   229376
#define SO_B2   229888
#define SO_CS   230400
#define SO_CQ   230912
#define SM_BYTES 231424

__global__ __launch_bounds__(MLP_THREADS, 1)
void fused_mlp_kernel(const float* __restrict__ W1, const float* __restrict__ b1,
                      const float* __restrict__ W2, const float* __restrict__ b2) {
    extern __shared__ char smc[];
    float* OUT = (float*)(smc + SO_A);
    float* STG = (float*)(smc + SO_STG);
    float* B1S = (float*)(smc + SO_B1);
    float* B2S = (float*)(smc + SO_B2);
    float* CS  = (float*)(smc + SO_CS);
    float* CQ  = (float*)(smc + SO_CQ);
    const uint32_t sb = smem_u32(smc);

    const int tid    = threadIdx.x;
    const int lane   = tid & 31;
    const int warp   = tid >> 5;
    const int warp_m = warp & 3;
    const int warp_n = warp >> 2;
    const int gid    = lane >> 2;
    const int tig    = lane & 3;

    float* io = g_agg;

    for (int i4 = tid; i4 < 4096; i4 += MLP_THREADS) {
        int k  = i4 >> 5;
        int c4 = i4 & 31;
        float4 v1 = ((const float4*)W1)[i4];
        float4 v2 = ((const float4*)W2)[i4];
        #pragma unroll
        for (int e = 0; e < 4; e++) {
            float a = (e == 0) ? v1.x : (e == 1) ? v1.y : (e == 2) ? v1.z : v1.w;
            float b = (e == 0) ? v2.x : (e == 1) ? v2.y : (e == 2) ? v2.z : v2.w;
            int n = c4 * 4 + e;
            int off = bswz(n, k >> 3) + (k & 7) * 2;
            __nv_bfloat16 ah = __float2bfloat16(a);
            __nv_bfloat16 bh = __float2bfloat16(b);
            *(__nv_bfloat16*)(smc + SO_W1H + off) = ah;
            *(__nv_bfloat16*)(smc + SO_W1L + off) = __float2bfloat16(a - __bfloat162float(ah));
            *(__nv_bfloat16*)(smc + SO_W2H + off) = bh;
            *(__nv_bfloat16*)(smc + SO_W2L + off) = __float2bfloat16(b - __bfloat162float(bh));
        }
    }
    if (tid < 128) {
        B1S[tid] = b1[tid];
        B2S[tid] = b2[tid];
        CS[tid]  = 0.f;
        CQ[tid]  = 0.f;
    }

    {
        int t0 = blockIdx.x;
        if (t0 < NT64) {
            int base = t0 << 6;
            #pragma unroll
            for (int q = 0; q < 4; q++) {
                int ch  = q * MLP_THREADS + tid;
                int row = ch >> 5, c4 = ch & 31;
                int sz  = (base + row < N_NODES) ? 16 : 0;
                cp_async16(sb + SO_STG + ch * 16,
                           (const float4*)io + (size_t)(base + row) * 32 + c4, sz);
            }
        }
        cp_commit();
    }

    const int rA0 = warp_m * 16 + (lane & 15);
    const int jAh = lane >> 4;
    const int rB0 = warp_n * 32 + (lane & 7) + ((lane >> 4) << 3);
    const int jBh = (lane >> 3) & 1;

    for (int t = blockIdx.x; t < NT64; t += gridDim.x) {
        const int base  = t << 6;
        const int valid = min(64, N_NODES - base);

        cp_wait0();
        __syncthreads();

        // ---- 1) split STG -> Ahi/Alo bf16 ------------------------------------
        #pragma unroll
        for (int q = 0; q < 2; q++) {
            int f   = q * MLP_THREADS + tid;
            int row = f >> 4, j = f & 15;
            const float4* src = (const float4*)(STG + row * 128 + j * 8);
            float4 v0 = src[0], v1 = src[1];
            uint32_t ph[4] = {pack_hi(v0.x, v0.y), pack_hi(v0.z, v0.w),
                              pack_hi(v1.x, v1.y), pack_hi(v1.z, v1.w)};
            uint32_t pl[4] = {pack_lo(v0.x, v0.y), pack_lo(v0.z, v0.w),
                              pack_lo(v1.x, v1.y), pack_lo(v1.z, v1.w)};
            int off = bswz(row, j);
            *(uint4*)(smc + SO_A + off)         = make_uint4(ph[0], ph[1], ph[2], ph[3]);
            *(uint4*)(smc + SO_A + 16384 + off) = make_uint4(pl[0], pl[1], pl[2], pl[3]);
        }
        __syncthreads();

        {
            int tn = t + gridDim.x;
            if (tn < NT64) {
                int nb = tn << 6;
                #pragma unroll
                for (int q = 0; q < 4; q++) {
                    int ch  = q * MLP_THREADS + tid;
                    int row = ch >> 5, c4 = ch & 31;
                    int sz  = (nb + row < N_NODES) ? 16 : 0;
                    cp_async16(sb + SO_STG + ch * 16,
                               (const float4*)io + (size_t)(nb + row) * 32 + c4, sz);
                }
            }
            cp_commit();
        }

        float c[4][4];

        // ================= GEMM 1: mid = relu(A @ W1 + b1) ====================
        #pragma unroll
        for (int j = 0; j < 4; j++)
            #pragma unroll
            for (int e = 0; e < 4; e++) c[j][e] = 0.f;

        #pragma unroll 2
        for (int s = 0; s < 8; s++) {
            int jA = (s << 1) | jAh;
            uint32_t offA = (uint32_t)(rA0 * 256 + ((((jA ^ rA0) & 7) | (jA & 8)) << 4));
            int jB = (s << 1) | jBh;
            uint32_t offB = (uint32_t)(rB0 * 256 + ((((jB ^ rB0) & 7) | (jB & 8)) << 4));

            uint32_t ah[4], al[4], bh[2][4], bl[2][4];
            ldmx4(ah, sb + SO_A + offA);
            ldmx4(al, sb + SO_A + 16384 + offA);
            ldmx4(bh[0], sb + SO_W1H + offB);
            ldmx4(bh[1], sb + SO_W1H + offB + 4096);
            ldmx4(bl[0], sb + SO_W1L + offB);
            ldmx4(bl[1], sb + SO_W1L + offB + 4096);

            #pragma unroll
            for (int j = 0; j < 4; j++) {
                int p = j >> 1, q2 = (j & 1) << 1;
                mma_bf16(c[j], ah, bh[p][q2], bh[p][q2 + 1]);
                mma_bf16(c[j], ah, bl[p][q2], bl[p][q2 + 1]);
                mma_bf16(c[j], al, bh[p][q2], bh[p][q2 + 1]);
            }
        }

        {
            int r0 = warp_m * 16 + gid;
            #pragma unroll
            for (int j = 0; j < 4; j++) {
                int cc = warp_n * 32 + j * 8 + 2 * tig;
                float v0 = fmaxf(c[j][0] + B1S[cc],     0.f);
                float v1 = fmaxf(c[j][1] + B1S[cc + 1], 0.f);
                float v2 = fmaxf(c[j][2] + B1S[cc],     0.f);
                float v3 = fmaxf(c[j][3] + B1S[cc + 1], 0.f);
                int o0 = bswz(r0,     cc >> 3) + 4 * tig;
                int o1 = bswz(r0 + 8, cc >> 3) + 4 * tig;
                *(uint32_t*)(smc + SO_MID + o0)         = pack_hi(v0, v1);
                *(uint32_t*)(smc + SO_MID + 16384 + o0) = pack_lo(v0, v1);
                *(uint32_t*)(smc + SO_MID + o1)         = pack_hi(v2, v3);
                *(uint32_t*)(smc + SO_MID + 16384 + o1) = pack_lo(v2, v3);
            }
        }
        __syncthreads();

        // ================= GEMM 2: h2 = mid @ W2 + b2 =========================
        #pragma unroll
        for (int j = 0; j < 4; j++)
            #pragma unroll
            for (int e = 0; e < 4; e++) c[j][e] = 0.f;

        #pragma unroll 2
        for (int s = 0; s < 8; s++) {
            int jA = (s << 1) | jAh;
            uint32_t offA = (uint32_t)(rA0 * 256 + ((((jA ^ rA0) & 7) | (jA & 8)) << 4));
            int jB = (s << 1) | jBh;
            uint32_t offB = (uint32_t)(rB0 * 256 + ((((jB ^ rB0) & 7) | (jB & 8)) << 4));

            uint32_t ah[4], al[4], bh[2][4], bl[2][4];
            ldmx4(ah, sb + SO_MID + offA);
            ldmx4(al, sb + SO_MID + 16384 + offA);
            ldmx4(bh[0], sb + SO_W2H + offB);
            ldmx4(bh[1], sb + SO_W2H + offB + 4096);
            ldmx4(bl[0], sb + SO_W2L + offB);
            ldmx4(bl[1], sb + SO_W2L + offB + 4096);

            #pragma unroll
            for (int j = 0; j < 4; j++) {
                int p = j >> 1, q2 = (j & 1) << 1;
                mma_bf16(c[j], ah, bh[p][q2], bh[p][q2 + 1]);
                mma_bf16(c[j], ah, bl[p][q2], bl[p][q2 + 1]);
                mma_bf16(c[j], al, bh[p][q2], bh[p][q2 + 1]);
            }
        }

        {
            int r0 = warp_m * 16 + gid;
            #pragma unroll
            for (int j = 0; j < 4; j++) {
                int cc = warp_n * 32 + j * 8 + 2 * tig;
                float v0 = c[j][0] + B2S[cc];
                float v1 = c[j][1] + B2S[cc + 1];
                float v2 = c[j][2] + B2S[cc];
                float v3 = c[j][3] + B2S[cc + 1];
                *(float2*)&OUT[idxA(r0,     cc)] = make_float2(v0, v1);
                *(float2*)&OUT[idxA(r0 + 8, cc)] = make_float2(v2, v3);
            }
        }
        __syncthreads();

        {
            int col  = tid >> 2;
            int quar = tid & 3;
            int rbeg = quar * 16;
            int rend = min(rbeg + 16, valid);
            float s = 0.f, q = 0.f;
            for (int r = rbeg; r < rend; r++) {
                float v = OUT[idxA(r, col)];
                s += v; q += v * v;
            }
            atomicAdd(&CS[col], s);
            atomicAdd(&CQ[col], q);
        }
        #pragma unroll
        for (int q = 0; q < 4; q++) {
            int f   = q * MLP_THREADS + tid;
            int row = f >> 5, c4 = f & 31;
            if (row < valid) {
                int off = row * 128 + ((c4 ^ (row & 31)) << 2);
                float4 v = *(const float4*)(OUT + off);
                ((float4*)io)[(size_t)(base + row) * 32 + c4] = v;
            }
        }
    }

    __syncthreads();
    if (tid < 128) {
        atomicAdd(&g_colsum[tid], (double)CS[tid]);
        atomicAdd(&g_colsq [tid], (double)CQ[tid]);
    }
}

// ---------------- apply BN (fp32 coefs, 2 float4 per thread for MLP) ---------
#define BN_THREADS 512
__global__ void bn_apply_kernel(const float* __restrict__ gamma,
                                const float* __restrict__ beta,
                                float* __restrict__ out) {
    __shared__ float sc[D], sh[D];
    if (threadIdx.x < D) {
        int j = threadIdx.x;
        float sum = (float)g_colsum[j];
        float sq  = (float)g_colsq[j];
        float invN = 1.0f / (float)N_NODES;
        float mean = sum * invN;
        float var  = fmaxf(sq * invN - mean * mean, 0.f);
        float inv  = rsqrtf(var + EPS);
        float s    = gamma[j] * inv;
        sc[j] = s;
        sh[j] = beta[j] - mean * s;
    }
    __syncthreads();
    size_t n4 = (size_t)N_NODES * D / 4;
    size_t i0 = (size_t)blockIdx.x * (BN_THREADS * 2) + threadIdx.x;
    #pragma unroll
    for (int u = 0; u < 2; u++) {
        size_t i = i0 + (size_t)u * BN_THREADS;
        if (i < n4) {
            int c = (int)((i & 31) << 2);
            float4 h = reinterpret_cast<const float4*>(g_agg)[i];
            float4 o;
            o.x = h.x * sc[c + 0] + sh[c + 0];
            o.y = h.y * sc[c + 1] + sh[c + 1];
            o.z = h.z * sc[c + 2] + sh[c + 2];
            o.w = h.w * sc[c + 3] + sh[c + 3];
            reinterpret_cast<float4*>(out)[i] = o;
        }
    }
}

// ---------------- launcher ------------------------------------------------------
extern "C" void kernel_launch(void* const* d_in, const int* in_sizes, int n_in,
                              void* d_out, int out_size) {
    const float* x     = (const float*)d_in[0];
    const void*  ei    = d_in[1];
    const float* W1    = (const float*)d_in[2];
    const float* b1    = (const float*)d_in[3];
    const float* W2    = (const float*)d_in[4];
    const float* b2    = (const float*)d_in[5];
    const float* gamma = (const float*)d_in[6];
    const float* beta  = (const float*)d_in[7];
    float* out = (float*)d_out;

    cudaFuncSetAttribute(fused_mlp_kernel,
                         cudaFuncAttributeMaxDynamicSharedMemorySize, SM_BYTES);

    {
        int n4 = N_NODES * D / 4;
        init_kernel<<<(n4 + 255) / 256, 256>>>(x, (const int*)ei);
    }
    {
        int blocks = (E_EDGES + 7) / 8;   // 8 warps (256 threads) per block
        scatter_kernel<<<blocks, 256>>>(x, ei);
    }
    fused_mlp_kernel<<<152, MLP_THREADS, SM_BYTES>>>(W1, b1, W2, b2);
    {
        int n4 = N_NODES * D / 4;
        int per_block = BN_THREADS * 2;
        bn_apply_kernel<<<(n4 + per_block - 1) / per_block, BN_THREADS>>>(gamma, beta, out);
    }
}

// round 16
// speedup vs baseline: 1.6577x; 1.1633x over previous
#include <cuda_runtime.h>
#include <cuda_bf16.h>
#include <cstdint>
#include <math.h>

#define N_NODES 100000
#define D 128
#define E_EDGES 1600000
#define EPS 1e-5f
#define NT64 ((N_NODES + 63) / 64)   // 1563 tiles of 64 rows

// ---------------- scratch (device globals: no allocs allowed) ----------------
__device__ float  g_agg[(size_t)N_NODES * D];   // x + agg; then h2 (in-place)
__device__ double g_colsum[D];
__device__ double g_colsq [D];
__device__ int    g_idx_is64;

// ============================ helpers ========================================
__device__ __forceinline__ uint32_t smem_u32(const void* p) {
    uint32_t a;
    asm("{ .reg .u64 t; cvta.to.shared.u64 t, %1; cvt.u32.u64 %0, t; }"
        : "=r"(a) : "l"(p));
    return a;
}
__device__ __forceinline__ int bswz(int r, int j) {
    return r * 256 + ((((j ^ r) & 7) | (j & 8)) << 4);
}
__device__ __forceinline__ int idxA(int row, int col) {
    return row * 128 + (((col >> 2) ^ (row & 31)) << 2) + (col & 3);
}
__device__ __forceinline__ void ldmx4(uint32_t r[4], uint32_t addr) {
    asm volatile("ldmatrix.sync.aligned.m8n8.x4.shared.b16 {%0,%1,%2,%3}, [%4];"
                 : "=r"(r[0]), "=r"(r[1]), "=r"(r[2]), "=r"(r[3]) : "r"(addr));
}
__device__ __forceinline__ void mma_bf16(float c[4], const uint32_t a[4],
                                         uint32_t b0, uint32_t b1) {
    asm volatile(
        "mma.sync.aligned.m16n8k16.row.col.f32.bf16.bf16.f32 "
        "{%0,%1,%2,%3}, {%4,%5,%6,%7}, {%8,%9}, {%0,%1,%2,%3};"
        : "+f"(c[0]), "+f"(c[1]), "+f"(c[2]), "+f"(c[3])
        : "r"(a[0]), "r"(a[1]), "r"(a[2]), "r"(a[3]), "r"(b0), "r"(b1));
}
__device__ __forceinline__ void cp_async16(uint32_t s, const void* g, int src_sz) {
    asm volatile("cp.async.cg.shared.global [%0], [%1], 16, %2;"
                 :: "r"(s), "l"(g), "r"(src_sz) : "memory");
}
__device__ __forceinline__ void cp_commit() {
    asm volatile("cp.async.commit_group;" ::: "memory");
}
__device__ __forceinline__ void cp_wait0() {
    asm volatile("cp.async.wait_group 0;" ::: "memory");
}
__device__ __forceinline__ uint32_t pack_hi(float a, float b) {
    __nv_bfloat16 h0 = __float2bfloat16(a), h1 = __float2bfloat16(b);
    return (uint32_t)__bfloat16_as_ushort(h0)
         | ((uint32_t)__bfloat16_as_ushort(h1) << 16);
}
__device__ __forceinline__ uint32_t pack_lo(float a, float b) {
    __nv_bfloat16 h0 = __float2bfloat16(a), h1 = __float2bfloat16(b);
    __nv_bfloat16 l0 = __float2bfloat16(a - __bfloat162float(h0));
    __nv_bfloat16 l1 = __float2bfloat16(b - __bfloat162float(h1));
    return (uint32_t)__bfloat16_as_ushort(l0)
         | ((uint32_t)__bfloat16_as_ushort(l1) << 16);
}

// ---------------- kernel 1: agg = x, zero BN accums, detect idx dtype -------
__global__ void init_kernel(const float* __restrict__ x,
                            const int* __restrict__ ei32) {
    size_t i = (size_t)blockIdx.x * blockDim.x + threadIdx.x;
    size_t n4 = (size_t)N_NODES * D / 4;
    if (i < n4)
        reinterpret_cast<float4*>(g_agg)[i] = reinterpret_cast<const float4*>(x)[i];
    if (blockIdx.x == 0 && threadIdx.x < D) {
        g_colsum[threadIdx.x] = 0.0;
        g_colsq [threadIdx.x] = 0.0;
    }
    if (blockIdx.x == 0 && threadIdx.x == 0) {
        int is64 = 1;
        #pragma unroll 1
        for (int k = 0; k < 128; k++)
            if (ei32[2 * k + 1] != 0) { is64 = 0; break; }
        g_idx_is64 = is64;
    }
}

// ---------------- kernel 2: scatter-add, grid-stride, warp per edge ---------
__device__ __forceinline__ void red_add_v4(float* addr, float4 v) {
    asm volatile("red.global.add.v4.f32 [%0], {%1,%2,%3,%4};"
                 :: "l"(addr), "f"(v.x), "f"(v.y), "f"(v.z), "f"(v.w) : "memory");
}
#define SCATTER_BLOCKS 1216   // 8 CTAs/SM on 152 SMs
__global__ void scatter_kernel(const float* __restrict__ x,
                               const void* __restrict__ ei_raw) {
    const int nw   = (gridDim.x * blockDim.x) >> 5;
    const int w0   = (blockIdx.x * blockDim.x + threadIdx.x) >> 5;
    const int lane = threadIdx.x & 31;

    if (g_idx_is64) {
        const long long* ei = (const long long*)ei_raw;
        #pragma unroll 2
        for (int e = w0; e < E_EDGES; e += nw) {
            int r = (int)__ldg(ei + e);
            int c = (int)__ldg(ei + E_EDGES + e);
            float4 v = __ldg((const float4*)x + (size_t)c * 32 + lane);
            red_add_v4(g_agg + (size_t)r * D + lane * 4, v);
        }
    } else {
        const int* ei = (const int*)ei_raw;
        #pragma unroll 2
        for (int e = w0; e < E_EDGES; e += nw) {
            int r = __ldg(ei + e);
            int c = __ldg(ei + E_EDGES + e);
            float4 v = __ldg((const float4*)x + (size_t)c * 32 + lane);
            red_add_v4(g_agg + (size_t)r * D + lane * 4, v);
        }
    }
}

// ---------------- fused MLP kernel (R12 structure, verbatim) ----------------
#define MLP_THREADS 512
#define SO_W1H  0
#define SO_W1L  32768
#define SO_W2H  65536
#define SO_W2L  98304
#define SO_A    131072     // Ahi 16384 | Alo 16384 ; OUT f32 aliases all 32768
#define SO_MID  163840
#define SO_STG  196608
#define SO_B1   229376
#define SO_B2   229888
#define SO_CS   230400
#define SO_CQ   230912
#define SM_BYTES 231424

__global__ __launch_bounds__(MLP_THREADS, 1)
void fused_mlp_kernel(const float* __restrict__ W1, const float* __restrict__ b1,
                      const float* __restrict__ W2, const float* __restrict__ b2) {
    extern __shared__ char smc[];
    float* OUT = (float*)(smc + SO_A);
    float* STG = (float*)(smc + SO_STG);
    float* B1S = (float*)(smc + SO_B1);
    float* B2S = (float*)(smc + SO_B2);
    float* CS  = (float*)(smc + SO_CS);
    float* CQ  = (float*)(smc + SO_CQ);
    const uint32_t sb = smem_u32(smc);

    const int tid    = threadIdx.x;
    const int lane   = tid & 31;
    const int warp   = tid >> 5;
    const int warp_m = warp & 3;
    const int warp_n = warp >> 2;
    const int gid    = lane >> 2;
    const int tig    = lane & 3;

    float* io = g_agg;

    for (int i4 = tid; i4 < 4096; i4 += MLP_THREADS) {
        int k  = i4 >> 5;
        int c4 = i4 & 31;
        float4 v1 = ((const float4*)W1)[i4];
        float4 v2 = ((const float4*)W2)[i4];
        #pragma unroll
        for (int e = 0; e < 4; e++) {
            float a = (e == 0) ? v1.x : (e == 1) ? v1.y : (e == 2) ? v1.z : v1.w;
            float b = (e == 0) ? v2.x : (e == 1) ? v2.y : (e == 2) ? v2.z : v2.w;
            int n = c4 * 4 + e;
            int off = bswz(n, k >> 3) + (k & 7) * 2;
            __nv_bfloat16 ah = __float2bfloat16(a);
            __nv_bfloat16 bh = __float2bfloat16(b);
            *(__nv_bfloat16*)(smc + SO_W1H + off) = ah;
            *(__nv_bfloat16*)(smc + SO_W1L + off) = __float2bfloat16(a - __bfloat162float(ah));
            *(__nv_bfloat16*)(smc + SO_W2H + off) = bh;
            *(__nv_bfloat16*)(smc + SO_W2L + off) = __float2bfloat16(b - __bfloat162float(bh));
        }
    }
    if (tid < 128) {
        B1S[tid] = b1[tid];
        B2S[tid] = b2[tid];
        CS[tid]  = 0.f;
        CQ[tid]  = 0.f;
    }

    {
        int t0 = blockIdx.x;
        if (t0 < NT64) {
            int base = t0 << 6;
            #pragma unroll
            for (int q = 0; q < 4; q++) {
                int ch  = q * MLP_THREADS + tid;
                int row = ch >> 5, c4 = ch & 31;
                int sz  = (base + row < N_NODES) ? 16 : 0;
                cp_async16(sb + SO_STG + ch * 16,
                           (const float4*)io + (size_t)(base + row) * 32 + c4, sz);
            }
        }
        cp_commit();
    }

    const int rA0 = warp_m * 16 + (lane & 15);
    const int jAh = lane >> 4;
    const int rB0 = warp_n * 32 + (lane & 7) + ((lane >> 4) << 3);
    const int jBh = (lane >> 3) & 1;

    for (int t = blockIdx.x; t < NT64; t += gridDim.x) {
        const int base  = t << 6;
        const int valid = min(64, N_NODES - base);

        cp_wait0();
        __syncthreads();

        // ---- 1) split STG -> Ahi/Alo bf16 ------------------------------------
        #pragma unroll
        for (int q = 0; q < 2; q++) {
            int f   = q * MLP_THREADS + tid;
            int row = f >> 4, j = f & 15;
            const float4* src = (const float4*)(STG + row * 128 + j * 8);
            float4 v0 = src[0], v1 = src[1];
            uint32_t ph[4] = {pack_hi(v0.x, v0.y), pack_hi(v0.z, v0.w),
                              pack_hi(v1.x, v1.y), pack_hi(v1.z, v1.w)};
            uint32_t pl[4] = {pack_lo(v0.x, v0.y), pack_lo(v0.z, v0.w),
                              pack_lo(v1.x, v1.y), pack_lo(v1.z, v1.w)};
            int off = bswz(row, j);
            *(uint4*)(smc + SO_A + off)         = make_uint4(ph[0], ph[1], ph[2], ph[3]);
            *(uint4*)(smc + SO_A + 16384 + off) = make_uint4(pl[0], pl[1], pl[2], pl[3]);
        }
        __syncthreads();

        {
            int tn = t + gridDim.x;
            if (tn < NT64) {
                int nb = tn << 6;
                #pragma unroll
                for (int q = 0; q < 4; q++) {
                    int ch  = q * MLP_THREADS + tid;
                    int row = ch >> 5, c4 = ch & 31;
                    int sz  = (nb + row < N_NODES) ? 16 : 0;
                    cp_async16(sb + SO_STG + ch * 16,
                               (const float4*)io + (size_t)(nb + row) * 32 + c4, sz);
                }
            }
            cp_commit();
        }

        float c[4][4];

        // ================= GEMM 1: mid = relu(A @ W1 + b1) ====================
        #pragma unroll
        for (int j = 0; j < 4; j++)
            #pragma unroll
            for (int e = 0; e < 4; e++) c[j][e] = 0.f;

        #pragma unroll 2
        for (int s = 0; s < 8; s++) {
            int jA = (s << 1) | jAh;
            uint32_t offA = (uint32_t)(rA0 * 256 + ((((jA ^ rA0) & 7) | (jA & 8)) << 4));
            int jB = (s << 1) | jBh;
            uint32_t offB = (uint32_t)(rB0 * 256 + ((((jB ^ rB0) & 7) | (jB & 8)) << 4));

            uint32_t ah[4], al[4], bh[2][4], bl[2][4];
            ldmx4(ah, sb + SO_A + offA);
            ldmx4(al, sb + SO_A + 16384 + offA);
            ldmx4(bh[0], sb + SO_W1H + offB);
            ldmx4(bh[1], sb + SO_W1H + offB + 4096);
            ldmx4(bl[0], sb + SO_W1L + offB);
            ldmx4(bl[1], sb + SO_W1L + offB + 4096);

            #pragma unroll
            for (int j = 0; j < 4; j++) {
                int p = j >> 1, q2 = (j & 1) << 1;
                mma_bf16(c[j], ah, bh[p][q2], bh[p][q2 + 1]);
                mma_bf16(c[j], ah, bl[p][q2], bl[p][q2 + 1]);
                mma_bf16(c[j], al, bh[p][q2], bh[p][q2 + 1]);
            }
        }

        {
            int r0 = warp_m * 16 + gid;
            #pragma unroll
            for (int j = 0; j < 4; j++) {
                int cc = warp_n * 32 + j * 8 + 2 * tig;
                float v0 = fmaxf(c[j][0] + B1S[cc],     0.f);
                float v1 = fmaxf(c[j][1] + B1S[cc + 1], 0.f);
                float v2 = fmaxf(c[j][2] + B1S[cc],     0.f);
                float v3 = fmaxf(c[j][3] + B1S[cc + 1], 0.f);
                int o0 = bswz(r0,     cc >> 3) + 4 * tig;
                int o1 = bswz(r0 + 8, cc >> 3) + 4 * tig;
                *(uint32_t*)(smc + SO_MID + o0)         = pack_hi(v0, v1);
                *(uint32_t*)(smc + SO_MID + 16384 + o0) = pack_lo(v0, v1);
                *(uint32_t*)(smc + SO_MID + o1)         = pack_hi(v2, v3);
                *(uint32_t*)(smc + SO_MID + 16384 + o1) = pack_lo(v2, v3);
            }
        }
        __syncthreads();

        // ================= GEMM 2: h2 = mid @ W2 + b2 =========================
        #pragma unroll
        for (int j = 0; j < 4; j++)
            #pragma unroll
            for (int e = 0; e < 4; e++) c[j][e] = 0.f;

        #pragma unroll 2
        for (int s = 0; s < 8; s++) {
            int jA = (s << 1) | jAh;
            uint32_t offA = (uint32_t)(rA0 * 256 + ((((jA ^ rA0) & 7) | (jA & 8)) << 4));
            int jB = (s << 1) | jBh;
            uint32_t offB = (uint32_t)(rB0 * 256 + ((((jB ^ rB0) & 7) | (jB & 8)) << 4));

            uint32_t ah[4], al[4], bh[2][4], bl[2][4];
            ldmx4(ah, sb + SO_MID + offA);
            ldmx4(al, sb + SO_MID + 16384 + offA);
            ldmx4(bh[0], sb + SO_W2H + offB);
            ldmx4(bh[1], sb + SO_W2H + offB + 4096);
            ldmx4(bl[0], sb + SO_W2L + offB);
            ldmx4(bl[1], sb + SO_W2L + offB + 4096);

            #pragma unroll
            for (int j = 0; j < 4; j++) {
                int p = j >> 1, q2 = (j & 1) << 1;
                mma_bf16(c[j], ah, bh[p][q2], bh[p][q2 + 1]);
                mma_bf16(c[j], ah, bl[p][q2], bl[p][q2 + 1]);
                mma_bf16(c[j], al, bh[p][q2], bh[p][q2 + 1]);
            }
        }

        {
            int r0 = warp_m * 16 + gid;
            #pragma unroll
            for (int j = 0; j < 4; j++) {
                int cc = warp_n * 32 + j * 8 + 2 * tig;
                float v0 = c[j][0] + B2S[cc];
                float v1 = c[j][1] + B2S[cc + 1];
                float v2 = c[j][2] + B2S[cc];
                float v3 = c[j][3] + B2S[cc + 1];
                *(float2*)&OUT[idxA(r0,     cc)] = make_float2(v0, v1);
                *(float2*)&OUT[idxA(r0 + 8, cc)] = make_float2(v2, v3);
            }
        }
        __syncthreads();

        {
            int col  = tid >> 2;
            int quar = tid & 3;
            int rbeg = quar * 16;
            int rend = min(rbeg + 16, valid);
            float s = 0.f, q = 0.f;
            for (int r = rbeg; r < rend; r++) {
                float v = OUT[idxA(r, col)];
                s += v; q += v * v;
            }
            atomicAdd(&CS[col], s);
            atomicAdd(&CQ[col], q);
        }
        #pragma unroll
        for (int q = 0; q < 4; q++) {
            int f   = q * MLP_THREADS + tid;
            int row = f >> 5, c4 = f & 31;
            if (row < valid) {
                int off = row * 128 + ((c4 ^ (row & 31)) << 2);
                float4 v = *(const float4*)(OUT + off);
                ((float4*)io)[(size_t)(base + row) * 32 + c4] = v;
            }
        }
    }

    __syncthreads();
    if (tid < 128) {
        atomicAdd(&g_colsum[tid], (double)CS[tid]);
        atomicAdd(&g_colsq [tid], (double)CQ[tid]);
    }
}

// ---------------- apply BN (fp32 coefs, 2 float4 per thread for MLP) ---------
#define BN_THREADS 512
__global__ void bn_apply_kernel(const float* __restrict__ gamma,
                                const float* __restrict__ beta,
                                float* __restrict__ out) {
    __shared__ float sc[D], sh[D];
    if (threadIdx.x < D) {
        int j = threadIdx.x;
        float sum = (float)g_colsum[j];
        float sq  = (float)g_colsq[j];
        float invN = 1.0f / (float)N_NODES;
        float mean = sum * invN;
        float var  = fmaxf(sq * invN - mean * mean, 0.f);
        float inv  = rsqrtf(var + EPS);
        float s    = gamma[j] * inv;
        sc[j] = s;
        sh[j] = beta[j] - mean * s;
    }
    __syncthreads();
    size_t n4 = (size_t)N_NODES * D / 4;
    size_t i0 = (size_t)blockIdx.x * (BN_THREADS * 2) + threadIdx.x;
    #pragma unroll
    for (int u = 0; u < 2; u++) {
        size_t i = i0 + (size_t)u * BN_THREADS;
        if (i < n4) {
            int c = (int)((i & 31) << 2);
            float4 h = reinterpret_cast<const float4*>(g_agg)[i];
            float4 o;
            o.x = h.x * sc[c + 0] + sh[c + 0];
            o.y = h.y * sc[c + 1] + sh[c + 1];
            o.z = h.z * sc[c + 2] + sh[c + 2];
            o.w = h.w * sc[c + 3] + sh[c + 3];
            reinterpret_cast<float4*>(out)[i] = o;
        }
    }
}

// ---------------- launcher ------------------------------------------------------
extern "C" void kernel_launch(void* const* d_in, const int* in_sizes, int n_in,
                              void* d_out, int out_size) {
    const float* x     = (const float*)d_in[0];
    const void*  ei    = d_in[1];
    const float* W1    = (const float*)d_in[2];
    const float* b1    = (const float*)d_in[3];
    const float* W2    = (const float*)d_in[4];
    const float* b2    = (const float*)d_in[5];
    const float* gamma = (const float*)d_in[6];
    const float* beta  = (const float*)d_in[7];
    float* out = (float*)d_out;

    cudaFuncSetAttribute(fused_mlp_kernel,
                         cudaFuncAttributeMaxDynamicSharedMemorySize, SM_BYTES);

    {
        int n4 = N_NODES * D / 4;
        init_kernel<<<(n4 + 255) / 256, 256>>>(x, (const int*)ei);
    }
    scatter_kernel<<<SCATTER_BLOCKS, 256>>>(x, ei);
    fused_mlp_kernel<<<152, MLP_THREADS, SM_BYTES>>>(W1, b1, W2, b2);
    {
        int n4 = N_NODES * D / 4;
        int per_block = BN_THREADS * 2;
        bn_apply_kernel<<<(n4 + per_block - 1) / per_block, BN_THREADS>>>(gamma, beta, out);
    }
}

// round 17
// speedup vs baseline: 1.6697x; 1.0072x over previous
#include <cuda_runtime.h>
#include <cuda_bf16.h>
#include <cstdint>
#include <math.h>

#define N_NODES 100000
#define D 128
#define E_EDGES 1600000
#define EPS 1e-5f
#define NT64 ((N_NODES + 63) / 64)   // 1563 tiles of 64 rows

// ---------------- scratch (device globals: no allocs allowed) ----------------
__device__ float  g_agg[(size_t)N_NODES * D];   // x + agg; then h2 (in-place)
__device__ double g_colsum[D];
__device__ double g_colsq [D];
__device__ int    g_idx_is64;

// ============================ helpers ========================================
__device__ __forceinline__ uint32_t smem_u32(const void* p) {
    uint32_t a;
    asm("{ .reg .u64 t; cvta.to.shared.u64 t, %1; cvt.u32.u64 %0, t; }"
        : "=r"(a) : "l"(p));
    return a;
}
__device__ __forceinline__ int bswz(int r, int j) {
    return r * 256 + ((((j ^ r) & 7) | (j & 8)) << 4);
}
__device__ __forceinline__ int idxA(int row, int col) {
    return row * 128 + (((col >> 2) ^ (row & 31)) << 2) + (col & 3);
}
__device__ __forceinline__ void ldmx4(uint32_t r[4], uint32_t addr) {
    asm volatile("ldmatrix.sync.aligned.m8n8.x4.shared.b16 {%0,%1,%2,%3}, [%4];"
                 : "=r"(r[0]), "=r"(r[1]), "=r"(r[2]), "=r"(r[3]) : "r"(addr));
}
__device__ __forceinline__ void mma_bf16(float c[4], const uint32_t a[4],
                                         uint32_t b0, uint32_t b1) {
    asm volatile(
        "mma.sync.aligned.m16n8k16.row.col.f32.bf16.bf16.f32 "
        "{%0,%1,%2,%3}, {%4,%5,%6,%7}, {%8,%9}, {%0,%1,%2,%3};"
        : "+f"(c[0]), "+f"(c[1]), "+f"(c[2]), "+f"(c[3])
        : "r"(a[0]), "r"(a[1]), "r"(a[2]), "r"(a[3]), "r"(b0), "r"(b1));
}
__device__ __forceinline__ void cp_async16(uint32_t s, const void* g, int src_sz) {
    asm volatile("cp.async.cg.shared.global [%0], [%1], 16, %2;"
                 :: "r"(s), "l"(g), "r"(src_sz) : "memory");
}
__device__ __forceinline__ void cp_commit() {
    asm volatile("cp.async.commit_group;" ::: "memory");
}
__device__ __forceinline__ void cp_wait0() {
    asm volatile("cp.async.wait_group 0;" ::: "memory");
}
__device__ __forceinline__ uint32_t pack_hi(float a, float b) {
    __nv_bfloat16 h0 = __float2bfloat16(a), h1 = __float2bfloat16(b);
    return (uint32_t)__bfloat16_as_ushort(h0)
         | ((uint32_t)__bfloat16_as_ushort(h1) << 16);
}
__device__ __forceinline__ uint32_t pack_lo(float a, float b) {
    __nv_bfloat16 h0 = __float2bfloat16(a), h1 = __float2bfloat16(b);
    __nv_bfloat16 l0 = __float2bfloat16(a - __bfloat162float(h0));
    __nv_bfloat16 l1 = __float2bfloat16(b - __bfloat162float(h1));
    return (uint32_t)__bfloat16_as_ushort(l0)
         | ((uint32_t)__bfloat16_as_ushort(l1) << 16);
}

// ---------------- kernel 1: agg = x, zero BN accums, detect idx dtype -------
__global__ void init_kernel(const float* __restrict__ x,
                            const int* __restrict__ ei32) {
    size_t i = (size_t)blockIdx.x * blockDim.x + threadIdx.x;
    size_t n4 = (size_t)N_NODES * D / 4;
    if (i < n4)
        reinterpret_cast<float4*>(g_agg)[i] = reinterpret_cast<const float4*>(x)[i];
    if (blockIdx.x == 0 && threadIdx.x < D) {
        g_colsum[threadIdx.x] = 0.0;
        g_colsq [threadIdx.x] = 0.0;
    }
    if (blockIdx.x == 0 && threadIdx.x == 0) {
        int is64 = 1;
        #pragma unroll 1
        for (int k = 0; k < 128; k++)
            if (ei32[2 * k + 1] != 0) { is64 = 0; break; }
        g_idx_is64 = is64;
    }
}

// ---------------- kernel 2: scatter-add, persistent, 4-way batched ----------
__device__ __forceinline__ void red_add_v4(float* addr, float4 v) {
    asm volatile("red.global.add.v4.f32 [%0], {%1,%2,%3,%4};"
                 :: "l"(addr), "f"(v.x), "f"(v.y), "f"(v.z), "f"(v.w) : "memory");
}
#define SCATTER_BLOCKS 1216   // 8 CTAs/SM on 152 SMs (64 warps/SM)
__global__ void scatter_kernel(const float* __restrict__ x,
                               const void* __restrict__ ei_raw) {
    const int nw   = (gridDim.x * blockDim.x) >> 5;     // total warps
    const int w0   = (blockIdx.x * blockDim.x + threadIdx.x) >> 5;
    const int lane = threadIdx.x & 31;
    const int nw4  = nw << 2;

    const long long* ei64 = (const long long*)ei_raw;
    const int*       ei32 = (const int*)ei_raw;
    const bool is64 = (g_idx_is64 != 0);

    #pragma unroll 1
    for (int e = w0; e < E_EDGES; e += nw4) {
        int  rr[4], cc[4];
        bool ok[4];
        // 1) batch the index loads (independent)
        #pragma unroll
        for (int u = 0; u < 4; u++) {
            int ee = e + u * nw;
            ok[u] = (ee < E_EDGES);
            rr[u] = 0; cc[u] = 0;
            if (ok[u]) {
                if (is64) {
                    rr[u] = (int)__ldg(ei64 + ee);
                    cc[u] = (int)__ldg(ei64 + E_EDGES + ee);
                } else {
                    rr[u] = __ldg(ei32 + ee);
                    cc[u] = __ldg(ei32 + E_EDGES + ee);
                }
            }
        }
        // 2) batch the gathers (MLP = 4)
        float4 v[4];
        #pragma unroll
        for (int u = 0; u < 4; u++)
            if (ok[u]) v[u] = __ldg((const float4*)x + (size_t)cc[u] * 32 + lane);
        // 3) fire-and-forget reductions
        #pragma unroll
        for (int u = 0; u < 4; u++)
            if (ok[u]) red_add_v4(g_agg + (size_t)rr[u] * D + lane * 4, v[u]);
    }
}

// ---------------- fused MLP kernel (R12 structure, verbatim) ----------------
#define MLP_THREADS 512
#define SO_W1H  0
#define SO_W1L  32768
#define SO_W2H  65536
#define SO_W2L  98304
#define SO_A    131072     // Ahi 16384 | Alo 16384 ; OUT f32 aliases all 32768
#define SO_MID  163840
#define SO_STG  196608
#define SO_B1   229376
#define SO_B2   229888
#define SO_CS   230400
#define SO_CQ   230912
#define SM_BYTES 231424

__global__ __launch_bounds__(MLP_THREADS, 1)
void fused_mlp_kernel(const float* __restrict__ W1, const float* __restrict__ b1,
                      const float* __restrict__ W2, const float* __restrict__ b2) {
    extern __shared__ char smc[];
    float* OUT = (float*)(smc + SO_A);
    float* STG = (float*)(smc + SO_STG);
    float* B1S = (float*)(smc + SO_B1);
    float* B2S = (float*)(smc + SO_B2);
    float* CS  = (float*)(smc + SO_CS);
    float* CQ  = (float*)(smc + SO_CQ);
    const uint32_t sb = smem_u32(smc);

    const int tid    = threadIdx.x;
    const int lane   = tid & 31;
    const int warp   = tid >> 5;
    const int warp_m = warp & 3;
    const int warp_n = warp >> 2;
    const int gid    = lane >> 2;
    const int tig    = lane & 3;

    float* io = g_agg;

    for (int i4 = tid; i4 < 4096; i4 += MLP_THREADS) {
        int k  = i4 >> 5;
        int c4 = i4 & 31;
        float4 v1 = ((const float4*)W1)[i4];
        float4 v2 = ((const float4*)W2)[i4];
        #pragma unroll
        for (int e = 0; e < 4; e++) {
            float a = (e == 0) ? v1.x : (e == 1) ? v1.y : (e == 2) ? v1.z : v1.w;
            float b = (e == 0) ? v2.x : (e == 1) ? v2.y : (e == 2) ? v2.z : v2.w;
            int n = c4 * 4 + e;
            int off = bswz(n, k >> 3) + (k & 7) * 2;
            __nv_bfloat16 ah = __float2bfloat16(a);
            __nv_bfloat16 bh = __float2bfloat16(b);
            *(__nv_bfloat16*)(smc + SO_W1H + off) = ah;
            *(__nv_bfloat16*)(smc + SO_W1L + off) = __float2bfloat16(a - __bfloat162float(ah));
            *(__nv_bfloat16*)(smc + SO_W2H + off) = bh;
            *(__nv_bfloat16*)(smc + SO_W2L + off) = __float2bfloat16(b - __bfloat162float(bh));
        }
    }
    if (tid < 128) {
        B1S[tid] = b1[tid];
        B2S[tid] = b2[tid];
        CS[tid]  = 0.f;
        CQ[tid]  = 0.f;
    }

    {
        int t0 = blockIdx.x;
        if (t0 < NT64) {
            int base = t0 << 6;
            #pragma unroll
            for (int q = 0; q < 4; q++) {
                int ch  = q * MLP_THREADS + tid;
                int row = ch >> 5, c4 = ch & 31;
                int sz  = (base + row < N_NODES) ? 16 : 0;
                cp_async16(sb + SO_STG + ch * 16,
                           (const float4*)io + (size_t)(base + row) * 32 + c4, sz);
            }
        }
        cp_commit();
    }

    const int rA0 = warp_m * 16 + (lane & 15);
    const int jAh = lane >> 4;
    const int rB0 = warp_n * 32 + (lane & 7) + ((lane >> 4) << 3);
    const int jBh = (lane >> 3) & 1;

    for (int t = blockIdx.x; t < NT64; t += gridDim.x) {
        const int base  = t << 6;
        const int valid = min(64, N_NODES - base);

        cp_wait0();
        __syncthreads();

        // ---- 1) split STG -> Ahi/Alo bf16 ------------------------------------
        #pragma unroll
        for (int q = 0; q < 2; q++) {
            int f   = q * MLP_THREADS + tid;
            int row = f >> 4, j = f & 15;
            const float4* src = (const float4*)(STG + row * 128 + j * 8);
            float4 v0 = src[0], v1 = src[1];
            uint32_t ph[4] = {pack_hi(v0.x, v0.y), pack_hi(v0.z, v0.w),
                              pack_hi(v1.x, v1.y), pack_hi(v1.z, v1.w)};
            uint32_t pl[4] = {pack_lo(v0.x, v0.y), pack_lo(v0.z, v0.w),
                              pack_lo(v1.x, v1.y), pack_lo(v1.z, v1.w)};
            int off = bswz(row, j);
            *(uint4*)(smc + SO_A + off)         = make_uint4(ph[0], ph[1], ph[2], ph[3]);
            *(uint4*)(smc + SO_A + 16384 + off) = make_uint4(pl[0], pl[1], pl[2], pl[3]);
        }
        __syncthreads();

        {
            int tn = t + gridDim.x;
            if (tn < NT64) {
                int nb = tn << 6;
                #pragma unroll
                for (int q = 0; q < 4; q++) {
                    int ch  = q * MLP_THREADS + tid;
                    int row = ch >> 5, c4 = ch & 31;
                    int sz  = (nb + row < N_NODES) ? 16 : 0;
                    cp_async16(sb + SO_STG + ch * 16,
                               (const float4*)io + (size_t)(nb + row) * 32 + c4, sz);
                }
            }
            cp_commit();
        }

        float c[4][4];

        // ================= GEMM 1: mid = relu(A @ W1 + b1) ====================
        #pragma unroll
        for (int j = 0; j < 4; j++)
            #pragma unroll
            for (int e = 0; e < 4; e++) c[j][e] = 0.f;

        #pragma unroll 2
        for (int s = 0; s < 8; s++) {
            int jA = (s << 1) | jAh;
            uint32_t offA = (uint32_t)(rA0 * 256 + ((((jA ^ rA0) & 7) | (jA & 8)) << 4));
            int jB = (s << 1) | jBh;
            uint32_t offB = (uint32_t)(rB0 * 256 + ((((jB ^ rB0) & 7) | (jB & 8)) << 4));

            uint32_t ah[4], al[4], bh[2][4], bl[2][4];
            ldmx4(ah, sb + SO_A + offA);
            ldmx4(al, sb + SO_A + 16384 + offA);
            ldmx4(bh[0], sb + SO_W1H + offB);
            ldmx4(bh[1], sb + SO_W1H + offB + 4096);
            ldmx4(bl[0], sb + SO_W1L + offB);
            ldmx4(bl[1], sb + SO_W1L + offB + 4096);

            #pragma unroll
            for (int j = 0; j < 4; j++) {
                int p = j >> 1, q2 = (j & 1) << 1;
                mma_bf16(c[j], ah, bh[p][q2], bh[p][q2 + 1]);
                mma_bf16(c[j], ah, bl[p][q2], bl[p][q2 + 1]);
                mma_bf16(c[j], al, bh[p][q2], bh[p][q2 + 1]);
            }
        }

        {
            int r0 = warp_m * 16 + gid;
            #pragma unroll
            for (int j = 0; j < 4; j++) {
                int cc = warp_n * 32 + j * 8 + 2 * tig;
                float v0 = fmaxf(c[j][0] + B1S[cc],     0.f);
                float v1 = fmaxf(c[j][1] + B1S[cc + 1], 0.f);
                float v2 = fmaxf(c[j][2] + B1S[cc],     0.f);
                float v3 = fmaxf(c[j][3] + B1S[cc + 1], 0.f);
                int o0 = bswz(r0,     cc >> 3) + 4 * tig;
                int o1 = bswz(r0 + 8, cc >> 3) + 4 * tig;
                *(uint32_t*)(smc + SO_MID + o0)         = pack_hi(v0, v1);
                *(uint32_t*)(smc + SO_MID + 16384 + o0) = pack_lo(v0, v1);
                *(uint32_t*)(smc + SO_MID + o1)         = pack_hi(v2, v3);
                *(uint32_t*)(smc + SO_MID + 16384 + o1) = pack_lo(v2, v3);
            }
        }
        __syncthreads();

        // ================= GEMM 2: h2 = mid @ W2 + b2 =========================
        #pragma unroll
        for (int j = 0; j < 4; j++)
            #pragma unroll
            for (int e = 0; e < 4; e++) c[j][e] = 0.f;

        #pragma unroll 2
        for (int s = 0; s < 8; s++) {
            int jA = (s << 1) | jAh;
            uint32_t offA = (uint32_t)(rA0 * 256 + ((((jA ^ rA0) & 7) | (jA & 8)) << 4));
            int jB = (s << 1) | jBh;
            uint32_t offB = (uint32_t)(rB0 * 256 + ((((jB ^ rB0) & 7) | (jB & 8)) << 4));

            uint32_t ah[4], al[4], bh[2][4], bl[2][4];
            ldmx4(ah, sb + SO_MID + offA);
            ldmx4(al, sb + SO_MID + 16384 + offA);
            ldmx4(bh[0], sb + SO_W2H + offB);
            ldmx4(bh[1], sb + SO_W2H + offB + 4096);
            ldmx4(bl[0], sb + SO_W2L + offB);
            ldmx4(bl[1], sb + SO_W2L + offB + 4096);

            #pragma unroll
            for (int j = 0; j < 4; j++) {
                int p = j >> 1, q2 = (j & 1) << 1;
                mma_bf16(c[j], ah, bh[p][q2], bh[p][q2 + 1]);
                mma_bf16(c[j], ah, bl[p][q2], bl[p][q2 + 1]);
                mma_bf16(c[j], al, bh[p][q2], bh[p][q2 + 1]);
            }
        }

        {
            int r0 = warp_m * 16 + gid;
            #pragma unroll
            for (int j = 0; j < 4; j++) {
                int cc = warp_n * 32 + j * 8 + 2 * tig;
                float v0 = c[j][0] + B2S[cc];
                float v1 = c[j][1] + B2S[cc + 1];
                float v2 = c[j][2] + B2S[cc];
                float v3 = c[j][3] + B2S[cc + 1];
                *(float2*)&OUT[idxA(r0,     cc)] = make_float2(v0, v1);
                *(float2*)&OUT[idxA(r0 + 8, cc)] = make_float2(v2, v3);
            }
        }
        __syncthreads();

        {
            int col  = tid >> 2;
            int quar = tid & 3;
            int rbeg = quar * 16;
            int rend = min(rbeg + 16, valid);
            float s = 0.f, q = 0.f;
            for (int r = rbeg; r < rend; r++) {
                float v = OUT[idxA(r, col)];
                s += v; q += v * v;
            }
            atomicAdd(&CS[col], s);
            atomicAdd(&CQ[col], q);
        }
        #pragma unroll
        for (int q = 0; q < 4; q++) {
            int f   = q * MLP_THREADS + tid;
            int row = f >> 5, c4 = f & 31;
            if (row < valid) {
                int off = row * 128 + ((c4 ^ (row & 31)) << 2);
                float4 v = *(const float4*)(OUT + off);
                ((float4*)io)[(size_t)(base + row) * 32 + c4] = v;
            }
        }
    }

    __syncthreads();
    if (tid < 128) {
        atomicAdd(&g_colsum[tid], (double)CS[tid]);
        atomicAdd(&g_colsq [tid], (double)CQ[tid]);
    }
}

// ---------------- apply BN (fp32 coefs, 2 float4 per thread for MLP) ---------
#define BN_THREADS 512
__global__ void bn_apply_kernel(const float* __restrict__ gamma,
                                const float* __restrict__ beta,
                                float* __restrict__ out) {
    __shared__ float sc[D], sh[D];
    if (threadIdx.x < D) {
        int j = threadIdx.x;
        float sum = (float)g_colsum[j];
        float sq  = (float)g_colsq[j];
        float invN = 1.0f / (float)N_NODES;
        float mean = sum * invN;
        float var  = fmaxf(sq * invN - mean * mean, 0.f);
        float inv  = rsqrtf(var + EPS);
        float s    = gamma[j] * inv;
        sc[j] = s;
        sh[j] = beta[j] - mean * s;
    }
    __syncthreads();
    size_t n4 = (size_t)N_NODES * D / 4;
    size_t i0 = (size_t)blockIdx.x * (BN_THREADS * 2) + threadIdx.x;
    #pragma unroll
    for (int u = 0; u < 2; u++) {
        size_t i = i0 + (size_t)u * BN_THREADS;
        if (i < n4) {
            int c = (int)((i & 31) << 2);
            float4 h = reinterpret_cast<const float4*>(g_agg)[i];
            float4 o;
            o.x = h.x * sc[c + 0] + sh[c + 0];
            o.y = h.y * sc[c + 1] + sh[c + 1];
            o.z = h.z * sc[c + 2] + sh[c + 2];
            o.w = h.w * sc[c + 3] + sh[c + 3];
            reinterpret_cast<float4*>(out)[i] = o;
        }
    }
}

// ---------------- launcher ------------------------------------------------------
extern "C" void kernel_launch(void* const* d_in, const int* in_sizes, int n_in,
                              void* d_out, int out_size) {
    const float* x     = (const float*)d_in[0];
    const void*  ei    = d_in[1];
    const float* W1    = (const float*)d_in[2];
    const float* b1    = (const float*)d_in[3];
    const float* W2    = (const float*)d_in[4];
    const float* b2    = (const float*)d_in[5];
    const float* gamma = (const float*)d_in[6];
    const float* beta  = (const float*)d_in[7];
    float* out = (float*)d_out;

    cudaFuncSetAttribute(fused_mlp_kernel,
                         cudaFuncAttributeMaxDynamicSharedMemorySize, SM_BYTES);

    {
        int n4 = N_NODES * D / 4;
        init_kernel<<<(n4 + 255) / 256, 256>>>(x, (const int*)ei);
    }
    scatter_kernel<<<SCATTER_BLOCKS, 256>>>(x, ei);
    fused_mlp_kernel<<<152, MLP_THREADS, SM_BYTES>>>(W1, b1, W2, b2);
    {
        int n4 = N_NODES * D / 4;
        int per_block = BN_THREADS * 2;
        bn_apply_kernel<<<(n4 + per_block - 1) / per_block, BN_THREADS>>>(gamma, beta, out);
    }
}